// round 17
// baseline (speedup 1.0000x reference)
#include <cuda_runtime.h>
#include <cuda_fp16.h>
#include <cstdint>

#define NTOK 4096
#define DDIM 1024
#define HDIM 2048
#define NEXP 8

// ---------------- scratch (static __device__, allocation-free) ----------------
__device__ __half g_xh [(size_t)NTOK * DDIM];               // fp16 x
__device__ __half g_hh [(size_t)NEXP * NTOK * HDIM];        // fp16 gelu(h) per slot
__device__ int    g_counts[NEXP];
__device__ int    g_tok  [NEXP * NTOK];                     // expert -> token list
__device__ float  g_gslot[NEXP * NTOK];                     // gate weight per slot

// ---------------- helpers ----------------
__device__ __forceinline__ void cpasync16(void* s, const void* g) {
    uint32_t sa = (uint32_t)__cvta_generic_to_shared(s);
    asm volatile("cp.async.cg.shared.global [%0], [%1], 16;" :: "r"(sa), "l"(g));
}
__device__ __forceinline__ void cp_commit() { asm volatile("cp.async.commit_group;"); }
__device__ __forceinline__ void cp_wait2()  { asm volatile("cp.async.wait_group 2;"); }

// fp16 MMA: m16n8k16, fp32 accum
__device__ __forceinline__ void mma_f16(float* c, const uint32_t* a, const uint32_t* b) {
    asm volatile(
        "mma.sync.aligned.m16n8k16.row.col.f32.f16.f16.f32 "
        "{%0,%1,%2,%3}, {%4,%5,%6,%7}, {%8,%9}, {%0,%1,%2,%3};"
        : "+f"(c[0]), "+f"(c[1]), "+f"(c[2]), "+f"(c[3])
        : "r"(a[0]), "r"(a[1]), "r"(a[2]), "r"(a[3]), "r"(b[0]), "r"(b[1]));
}
__device__ __forceinline__ void ldsm_x4(uint32_t* r, uint32_t saddr) {
    asm volatile("ldmatrix.sync.aligned.m8n8.x4.shared.b16 {%0,%1,%2,%3}, [%4];"
                 : "=r"(r[0]), "=r"(r[1]), "=r"(r[2]), "=r"(r[3]) : "r"(saddr));
}
__device__ __forceinline__ void ldsm_x4_t(uint32_t* r, uint32_t saddr) {
    asm volatile("ldmatrix.sync.aligned.m8n8.x4.trans.shared.b16 {%0,%1,%2,%3}, [%4];"
                 : "=r"(r[0]), "=r"(r[1]), "=r"(r[2]), "=r"(r[3]) : "r"(saddr));
}

// JAX default gelu: approximate=True (tanh form)
__device__ __forceinline__ float gelu_tanh(float v) {
    float t = tanhf(0.7978845608028654f * (v + 0.044715f * v * v * v));
    return 0.5f * v * (1.0f + t);
}

// ---------------- stage 0: zero out + counts (out receives atomic combine) ----------------
__global__ void zero_out_kernel(float4* __restrict__ out) {
    const int i = blockIdx.x * blockDim.x + threadIdx.x;
    out[i] = make_float4(0.f, 0.f, 0.f, 0.f);
    if (blockIdx.x == 0 && threadIdx.x < NEXP) g_counts[threadIdx.x] = 0;
}

// ---------------- stage 1: gating (32 tokens/block, smem-staged transposed w_gate) ----
// w_gate L2 traffic: 134 MB (per-token re-read) -> 4 MB (per-block stage).
__global__ void __launch_bounds__(256) gate_kernel(
    const float* __restrict__ x, const float* __restrict__ wg) {
    __shared__ float swgT[NEXP][DDIM];               // 32 KB, transposed: conflict-free LDS
    const int tid = threadIdx.x;
    for (int i = tid; i < DDIM * NEXP; i += 256) {
        const int d = i >> 3, e = i & 7;             // wg is [d][e], e fast
        swgT[e][d] = wg[i];
    }
    __syncthreads();

    const int wid = tid >> 5, lane = tid & 31;
#pragma unroll
    for (int wt = 0; wt < 4; wt++) {
        const int n = blockIdx.x * 32 + wid * 4 + wt;
        const float* xr = x + (size_t)n * DDIM;

        float acc[NEXP];
#pragma unroll
        for (int e = 0; e < NEXP; e++) acc[e] = 0.0f;
        for (int d = lane; d < DDIM; d += 32) {
            const float xv = xr[d];
            g_xh[(size_t)n * DDIM + d] = __float2half_rn(xv);   // fused x->fp16
#pragma unroll
            for (int e = 0; e < NEXP; e++) acc[e] += xv * swgT[e][d];
        }
#pragma unroll
        for (int e = 0; e < NEXP; e++) {
#pragma unroll
            for (int o = 16; o > 0; o >>= 1)
                acc[e] += __shfl_xor_sync(0xffffffffu, acc[e], o);
        }
        if (lane == 0) {
            int i0 = 0;
#pragma unroll
            for (int e = 1; e < NEXP; e++) if (acc[e] > acc[i0]) i0 = e;
            int i1 = (i0 == 0) ? 1 : 0;
#pragma unroll
            for (int e = 0; e < NEXP; e++) if (e != i0 && acc[e] > acc[i1]) i1 = e;
            const float e1 = __expf(acc[i1] - acc[i0]);
            const float inv = 1.0f / (1.0f + e1);

            const int s0 = atomicAdd(&g_counts[i0], 1);
            const int s1 = atomicAdd(&g_counts[i1], 1);
            g_tok[i0 * NTOK + s0] = n;   g_gslot[i0 * NTOK + s0] = inv;
            g_tok[i1 * NTOK + s1] = n;   g_gslot[i1 * NTOK + s1] = e1 * inv;
        }
    }
}

// ---------------- stages 2/3: grouped GEMM, fp16 mma.sync m16n8k16 ----------------
// Tile 128 x 128, BK=32, 256 thr. A (fp16 activations): 4-stage cp.async.
// B (weights): consumed DIRECTLY from fp32 gmem — LDG.128 x4 two iters ahead,
// in-register fp32->fp16 convert, STS into a 2-slot smem ring. Eliminates the
// standalone weight-conversion kernels (~33 us); the extra ~14 instr/thread/iter
// hide in the >50% free issue slots of this tensor-issue-bound loop.
// PHASE 2 epilogue fuses the top-2 combine via atomicAdd (2 contributions into
// a zeroed buffer: order-invariant, deterministic).

#define A_STRIDE 40          // halfs per A smem row (32 k + 8 pad)
#define B_STRIDE 136         // halfs per B smem row (128 n + 8 pad)
#define A_STAGE  (128 * A_STRIDE)            // 5120 halfs
#define B_STAGE  (32 * B_STRIDE)             // 4352 halfs
#define SMEM_HALFS (4 * A_STAGE + 2 * B_STAGE)
#define SMEM_BYTES (SMEM_HALFS * 2)          // 58,368 B

template <int PHASE>
__global__ void __launch_bounds__(256) ffn_gemm_kernel(
    const __half* __restrict__ x, const float* __restrict__ w_all,
    const float* __restrict__ bias_all, float* __restrict__ out) {
    constexpr int KD   = (PHASE == 1) ? DDIM : HDIM;
    constexpr int NOUT = (PHASE == 1) ? HDIM : DDIM;
    constexpr int KT   = KD / 32;

    const int e  = blockIdx.z;
    const int tm = blockIdx.y;
    const int tn = blockIdx.x;
    const int cnt = g_counts[e];
    if (tm * 128 >= cnt) return;
    const int rows = min(128, cnt - tm * 128);

    extern __shared__ __half smem[];
    __half* const Abase = smem;                      // 4 stages x A_STAGE
    __half* const Bbase = smem + 4 * A_STAGE;        // 2 slots  x B_STAGE
    const uint32_t sbase = (uint32_t)__cvta_generic_to_shared(smem);

    const int tid  = threadIdx.x;
    const int lane = tid & 31, wid = tid >> 5;
    const int wm = wid >> 2, wn = wid & 3;           // 2 x 4 warp grid, 64x32 per warp
    const int grp = lane >> 2, tig = lane & 3;

    // ---- A: cp.async assignments (fp16 source) ----
    const __half* ag[2];
    int aoff[2];
#pragma unroll
    for (int j = 0; j < 2; j++) {
        const int linear = j * 256 + tid;
        const int ar = linear >> 2;                  // row 0..127
        const int ac = (linear & 3) * 8;             // half offset 0/8/16/24
        if (PHASE == 1) {
            const int tk = g_tok[e * NTOK + tm * 128 + ar];
            ag[j] = x + (size_t)tk * DDIM + ac;
        } else {
            ag[j] = g_hh + ((size_t)e * NTOK + tm * 128 + ar) * HDIM + ac;
        }
        aoff[j] = ar * A_STRIDE + ac;
    }
    auto issueA = [&](int it, int stage) {
        __half* As = Abase + stage * A_STAGE;
        cpasync16(As + aoff[0], ag[0] + it * 32);
        cpasync16(As + aoff[1], ag[1] + it * 32);
    };

    // ---- B: fp32 gmem -> regs -> fp16 smem (2-slot ring, pipelined 2 ahead) ----
    // thread t: k-row t>>3 (0..31), col chunk (t&7)*16 (16 floats = 4 float4)
    const int brow = tid >> 3, bchunk = (tid & 7) * 16;
    const float* wsrc = w_all + (size_t)e * ((size_t)KD * NOUT);
    const float* bg = wsrc + (size_t)brow * NOUT + (size_t)tn * 128 + bchunk;
    const int bSts = brow * B_STRIDE + bchunk;       // half offset in B slot
    float4 bReg[4];
    auto ldgB = [&](int it) {
        const float4* p = (const float4*)(bg + (size_t)it * 32 * NOUT);
        bReg[0] = p[0]; bReg[1] = p[1]; bReg[2] = p[2]; bReg[3] = p[3];
    };
    auto stsB = [&](int slot) {
        __half2 h[8];
        h[0] = __floats2half2_rn(bReg[0].x, bReg[0].y);
        h[1] = __floats2half2_rn(bReg[0].z, bReg[0].w);
        h[2] = __floats2half2_rn(bReg[1].x, bReg[1].y);
        h[3] = __floats2half2_rn(bReg[1].z, bReg[1].w);
        h[4] = __floats2half2_rn(bReg[2].x, bReg[2].y);
        h[5] = __floats2half2_rn(bReg[2].z, bReg[2].w);
        h[6] = __floats2half2_rn(bReg[3].x, bReg[3].y);
        h[7] = __floats2half2_rn(bReg[3].z, bReg[3].w);
        uint4* d = (uint4*)(Bbase + slot * B_STAGE + bSts);  // 32B-aligned
        d[0] = *(uint4*)&h[0];
        d[1] = *(uint4*)&h[4];
    };

    // ---- ldmatrix lane address components ----
    const int l15 = lane & 15, lhi = lane >> 4;
    const int aLane = (wm * 64 + l15) * A_STRIDE + lhi * 8;
    const int bLane = l15 * B_STRIDE + wn * 32 + lhi * 8;

    float acc[4][4][4];
#pragma unroll
    for (int mi = 0; mi < 4; mi++)
#pragma unroll
        for (int ni = 0; ni < 4; ni++)
#pragma unroll
            for (int q = 0; q < 4; q++) acc[mi][ni][q] = 0.0f;

    // ---- prologue ----
    ldgB(0);
    issueA(0, 0); cp_commit();
    issueA(1, 1); cp_commit();
    issueA(2, 2); cp_commit();
    stsB(0);                                         // b(0) -> slot 0 (pre-barrier)
    ldgB(1);

    for (int it = 0; it < KT; it++) {
        const int stage = it & 3;
        cp_wait2();                                  // A stage `it` landed
        __syncthreads();                             // publishes stsB(it) + guards reuse
        if (it + 3 < KT) issueA(it + 3, (it + 3) & 3);
        cp_commit();                                 // empty commit at tail keeps count math
        if (it + 1 < KT) {
            stsB((it + 1) & 1);                      // b(it+1) -> other slot
            if (it + 2 < KT) ldgB(it + 2);
        }

        const uint32_t aSt = sbase + (uint32_t)((stage * A_STAGE + aLane) * 2);
        const uint32_t bSt = sbase + (uint32_t)((4 * A_STAGE + (it & 1) * B_STAGE + bLane) * 2);
#pragma unroll
        for (int ks = 0; ks < 2; ks++) {             // two k16 steps per BK=32
            uint32_t af[4][4], bf[4][2];
#pragma unroll
            for (int mi = 0; mi < 4; mi++)
                ldsm_x4(af[mi], aSt + (uint32_t)((mi * 16 * A_STRIDE + ks * 16) * 2));
#pragma unroll
            for (int p = 0; p < 2; p++) {
                uint32_t t[4];
                ldsm_x4_t(t, bSt + (uint32_t)((ks * 16 * B_STRIDE + p * 16) * 2));
                bf[2 * p][0] = t[0]; bf[2 * p][1] = t[1];
                bf[2 * p + 1][0] = t[2]; bf[2 * p + 1][1] = t[3];
            }
#pragma unroll
            for (int mi = 0; mi < 4; mi++)
#pragma unroll
                for (int ni = 0; ni < 4; ni++)
                    mma_f16(acc[mi][ni], af[mi], bf[ni]);
        }
        // no trailing sync: next iteration's leading sync protects reuse
    }

    // ---- epilogue ----
    const float* bias = bias_all + e * NOUT;
    const size_t rowbase = (size_t)e * NTOK + (size_t)tm * 128;
#pragma unroll
    for (int mi = 0; mi < 4; mi++) {
        const int lr0 = wm * 64 + mi * 16 + grp;
        const int lr1 = lr0 + 8;
        int   tk0 = 0, tk1 = 0;
        float gv0 = 0.f, gv1 = 0.f;
        if (PHASE == 2) {
            if (lr0 < rows) { tk0 = g_tok[rowbase + lr0]; gv0 = g_gslot[rowbase + lr0]; }
            if (lr1 < rows) { tk1 = g_tok[rowbase + lr1]; gv1 = g_gslot[rowbase + lr1]; }
        }
#pragma unroll
        for (int ni = 0; ni < 4; ni++) {
            const int col = tn * 128 + wn * 32 + ni * 8 + tig * 2;
            const float bv0 = bias[col], bv1 = bias[col + 1];
            float v00 = acc[mi][ni][0] + bv0, v01 = acc[mi][ni][1] + bv1;
            float v10 = acc[mi][ni][2] + bv0, v11 = acc[mi][ni][3] + bv1;
            if (PHASE == 1) {
                __half2 h0 = __floats2half2_rn(gelu_tanh(v00), gelu_tanh(v01));
                __half2 h1 = __floats2half2_rn(gelu_tanh(v10), gelu_tanh(v11));
                if (lr0 < rows)
                    *(__half2*)(g_hh + (rowbase + lr0) * HDIM + col) = h0;
                if (lr1 < rows)
                    *(__half2*)(g_hh + (rowbase + lr1) * HDIM + col) = h1;
            } else {
                if (lr0 < rows) {
                    float* o = out + (size_t)tk0 * DDIM + col;
                    atomicAdd(o,     gv0 * v00);
                    atomicAdd(o + 1, gv0 * v01);
                }
                if (lr1 < rows) {
                    float* o = out + (size_t)tk1 * DDIM + col;
                    atomicAdd(o,     gv1 * v10);
                    atomicAdd(o + 1, gv1 * v11);
                }
            }
        }
    }
}

// ---------------- launch ----------------
extern "C" void kernel_launch(void* const* d_in, const int* in_sizes, int n_in,
                              void* d_out, int out_size) {
    const float* x  = (const float*)d_in[0];   // [N, D]
    const float* wg = (const float*)d_in[1];   // [D, E]
    const float* w1 = (const float*)d_in[2];   // [E, D, H]
    const float* b1 = (const float*)d_in[3];   // [E, H]
    const float* w2 = (const float*)d_in[4];   // [E, H, D]
    const float* b2 = (const float*)d_in[5];   // [E, D]
    float* out = (float*)d_out;

    __half* xh; cudaGetSymbolAddress((void**)&xh, g_xh);

    cudaFuncSetAttribute(ffn_gemm_kernel<1>, cudaFuncAttributeMaxDynamicSharedMemorySize, SMEM_BYTES);
    cudaFuncSetAttribute(ffn_gemm_kernel<2>, cudaFuncAttributeMaxDynamicSharedMemorySize, SMEM_BYTES);

    // zero out (atomic-combine target) + counts in one launch
    zero_out_kernel<<<NTOK * DDIM / 4 / 256, 256>>>((float4*)out);

    gate_kernel<<<NTOK / 32, 256>>>(x, wg);    // also produces fp16 x

    // GEMMs consume fp32 weights directly (inline convert in B pipeline)
    ffn_gemm_kernel<1><<<dim3(HDIM / 128, NTOK / 128, NEXP), 256, SMEM_BYTES>>>(xh, w1, b1, out);
    ffn_gemm_kernel<2><<<dim3(DDIM / 128, NTOK / 128, NEXP), 256, SMEM_BYTES>>>(xh, w2, b2, out);
}